// round 1
// baseline (speedup 1.0000x reference)
#include <cuda_runtime.h>

// EMD / min-permutation matching:
//   B=32768 batches, N=6 points, D=64 dims.
//   best_cost[b] = min over perms of sum_n ||p_n - t_{pi(n)}||^2
//                = (sum of all squares) - 2 * maxAssign(G),  G[n][m] = p_n . t_m
//   out[0] = sum_b best_cost[b]
//
// Strategy: thread-per-batch. Shared memory is the global->per-thread transpose
// engine: coalesced float4 global loads -> SMEM -> conflict-free per-thread reads.
// Assignment min via subset DP (Held-Karp, 64 masks), fully unrolled in regs.

#define BLOCK   128
#define BPB     128          // batches per block (== BLOCK, 1 batch / thread)
#define DC      4            // d-chunk (floats) per iteration
#define NITER   16           // 64 / DC
#define SSTRIDE 52           // floats per batch in shared: 12 rows * 4 + 4 pad
                             // 52 % 32 == 20 (== 4 mod 8) -> LDS.128 conflict-free

__global__ __launch_bounds__(BLOCK, 4)
void emd_kernel(const float* __restrict__ preds,
                const float* __restrict__ targets,
                float* __restrict__ out, int B)
{
    __shared__ float sh[BPB * SSTRIDE];   // 26624 B
    __shared__ float wsum[BLOCK / 32];

    const int t  = threadIdx.x;
    const int b0 = blockIdx.x * BPB;

    float G[36];
#pragma unroll
    for (int i = 0; i < 36; ++i) G[i] = 0.0f;
    float sq = 0.0f;

    for (int it = 0; it < NITER; ++it) {
        const int d0 = it * DC;
        __syncthreads();   // protect sh reuse from previous iteration's readers

        // ---- load: 128 batches x 12 rows x 1 float4 = 1536 float4, 12/thread.
        // i = j*BLOCK + t; consecutive threads -> consecutive (bb,r) segments.
        // Every 16B load is a fully-used half-sector; all bytes read exactly once.
#pragma unroll
        for (int j = 0; j < 12; ++j) {
            unsigned i  = (unsigned)(j * BLOCK + t);   // 0..1535
            unsigned bb = i / 12u;
            unsigned r  = i % 12u;                     // 0..5 preds, 6..11 targets
            int b = b0 + (int)bb;
            if (b < B) {
                const float* src = (r < 6u)
                    ? preds   + (size_t)b * 384 + r * 64 + d0
                    : targets + (size_t)b * 384 + (r - 6u) * 64 + d0;
                float4 v = *(const float4*)src;
                *(float4*)&sh[bb * SSTRIDE + r * 4] = v;
            }
        }
        __syncthreads();

        // ---- compute: each thread consumes its own batch's chunk.
        const float* my = &sh[t * SSTRIDE];
        float4 p[6], q[6];
#pragma unroll
        for (int n = 0; n < 6; ++n) p[n] = *(const float4*)&my[n * 4];
#pragma unroll
        for (int m = 0; m < 6; ++m) q[m] = *(const float4*)&my[24 + m * 4];

#pragma unroll
        for (int n = 0; n < 6; ++n)
            sq += p[n].x*p[n].x + p[n].y*p[n].y + p[n].z*p[n].z + p[n].w*p[n].w;
#pragma unroll
        for (int m = 0; m < 6; ++m)
            sq += q[m].x*q[m].x + q[m].y*q[m].y + q[m].z*q[m].z + q[m].w*q[m].w;

#pragma unroll
        for (int n = 0; n < 6; ++n)
#pragma unroll
            for (int m = 0; m < 6; ++m)
                G[n * 6 + m] += p[n].x*q[m].x + p[n].y*q[m].y
                              + p[n].z*q[m].z + p[n].w*q[m].w;
    }

    // ---- assignment DP over subsets (maximize sum of G[row][m]).
    // dp[S] = best G-sum assigning rows 0..popc(S)-1 to target set S.
    // Fully unrolled: all indices constant -> dp stays in registers.
    float cost = 0.0f;
    if (b0 + t < B) {
        float dp[64];
        dp[0] = 0.0f;
#pragma unroll
        for (int S = 1; S < 64; ++S) {
            const int r = __popc((unsigned)S) - 1;
            float best = -3.0e38f;
#pragma unroll
            for (int m = 0; m < 6; ++m) {
                if (S & (1 << m)) {
                    float v = dp[S ^ (1 << m)] + G[r * 6 + m];
                    best = fmaxf(best, v);
                }
            }
            dp[S] = best;
        }
        cost = sq - 2.0f * dp[63];
    }

    // ---- block reduction -> one atomicAdd per block.
#pragma unroll
    for (int o = 16; o > 0; o >>= 1)
        cost += __shfl_down_sync(0xffffffffu, cost, o);
    if ((t & 31) == 0) wsum[t >> 5] = cost;
    __syncthreads();
    if (t == 0) {
        float s = 0.0f;
#pragma unroll
        for (int w = 0; w < BLOCK / 32; ++w) s += wsum[w];
        atomicAdd(out, s);
    }
}

extern "C" void kernel_launch(void* const* d_in, const int* in_sizes, int n_in,
                              void* d_out, int out_size)
{
    const float* preds   = (const float*)d_in[0];
    const float* targets = (const float*)d_in[1];
    const int B = in_sizes[0] / 384;   // 6 * 64 floats per batch

    cudaMemsetAsync(d_out, 0, sizeof(float));
    const int grid = (B + BPB - 1) / BPB;
    emd_kernel<<<grid, BLOCK>>>(preds, targets, (float*)d_out, B);
}

// round 2
// speedup vs baseline: 3.1841x; 3.1841x over previous
#include <cuda_runtime.h>

// EMD / min-permutation matching on GB300.
//   B=32768, N=6, D=64.
//   cost[b] = min_perm sum_n ||p_n - t_{pi(n)}||^2
//           = (sum of all squared norms) - 2 * maxAssign(G),  G[n][m] = p_n . t_m
//   out[0] = sum_b cost[b]
//
// R2 design: 8 threads per batch, no shared-memory staging, no syncs in the
// hot path. Thread j of a group owns dims [4j,4j+4) U [32+4j,32+4j+4), so
// every LDG.128 across the 8-lane group is a contiguous 128B segment
// (perfectly coalesced). Partial G[36] reduced over the 8 lanes via
// shfl_xor butterfly; lane j==0 runs the layered subset-DP (Held-Karp).

#define BLOCK 128

__global__ __launch_bounds__(BLOCK, 4)
void emd_kernel(const float* __restrict__ preds,
                const float* __restrict__ targets,
                float* __restrict__ out, int B)
{
    const int g    = blockIdx.x * BLOCK + threadIdx.x;
    const int bRaw = g >> 3;          // batch index
    const int j    = g & 7;           // lane within 8-thread group
    const bool valid = (bRaw < B);
    const int b = valid ? bRaw : (B - 1);   // clamp: keeps all lanes converged

    const float* pp = preds   + (size_t)b * 384 + 4 * j;
    const float* tt = targets + (size_t)b * 384 + 4 * j;

    // ---- load all 6 pred rows for this thread's 8 dims (12 independent LDG.128)
    float4 pa[6], pc[6];
#pragma unroll
    for (int n = 0; n < 6; ++n) {
        pa[n] = *(const float4*)(pp + n * 64);
        pc[n] = *(const float4*)(pp + n * 64 + 32);
    }

    float sq = 0.0f;
#pragma unroll
    for (int n = 0; n < 6; ++n) {
        sq += pa[n].x*pa[n].x + pa[n].y*pa[n].y + pa[n].z*pa[n].z + pa[n].w*pa[n].w;
        sq += pc[n].x*pc[n].x + pc[n].y*pc[n].y + pc[n].z*pc[n].z + pc[n].w*pc[n].w;
    }

    float G[36];
#pragma unroll
    for (int i = 0; i < 36; ++i) G[i] = 0.0f;

    // ---- stream target rows; accumulate partial Gram matrix
#pragma unroll
    for (int m = 0; m < 6; ++m) {
        float4 qa = *(const float4*)(tt + m * 64);
        float4 qc = *(const float4*)(tt + m * 64 + 32);
        sq += qa.x*qa.x + qa.y*qa.y + qa.z*qa.z + qa.w*qa.w;
        sq += qc.x*qc.x + qc.y*qc.y + qc.z*qc.z + qc.w*qc.w;
#pragma unroll
        for (int n = 0; n < 6; ++n) {
            G[n * 6 + m] += pa[n].x*qa.x + pa[n].y*qa.y + pa[n].z*qa.z + pa[n].w*qa.w
                          + pc[n].x*qc.x + pc[n].y*qc.y + pc[n].z*qc.z + pc[n].w*qc.w;
        }
    }

    // ---- butterfly reduce partial G and sq across the 8-lane group
#pragma unroll
    for (int o = 1; o < 8; o <<= 1) {
#pragma unroll
        for (int i = 0; i < 36; ++i)
            G[i] += __shfl_xor_sync(0xffffffffu, G[i], o);
        sq += __shfl_xor_sync(0xffffffffu, sq, o);
    }

    // ---- assignment DP (maximize), layered by popcount to bound liveness
    float cost = 0.0f;
    if (j == 0 && valid) {
        float dp[64];
        dp[0] = 0.0f;
#pragma unroll
        for (int k = 1; k <= 6; ++k) {
            const int r = k - 1;   // row being assigned at this layer
#pragma unroll
            for (int S = 1; S < 64; ++S) {
                if (__popc((unsigned)S) == k) {
                    float best = -3.0e38f;
#pragma unroll
                    for (int m = 0; m < 6; ++m)
                        if (S & (1 << m))
                            best = fmaxf(best, dp[S ^ (1 << m)] + G[r * 6 + m]);
                    dp[S] = best;
                }
            }
        }
        cost = sq - 2.0f * dp[63];
    }

    // ---- warp + block reduction, one atomicAdd per block
#pragma unroll
    for (int o = 16; o > 0; o >>= 1)
        cost += __shfl_down_sync(0xffffffffu, cost, o);

    __shared__ float wsum[BLOCK / 32];
    if ((threadIdx.x & 31) == 0) wsum[threadIdx.x >> 5] = cost;
    __syncthreads();
    if (threadIdx.x == 0) {
        float s = 0.0f;
#pragma unroll
        for (int w = 0; w < BLOCK / 32; ++w) s += wsum[w];
        atomicAdd(out, s);
    }
}

extern "C" void kernel_launch(void* const* d_in, const int* in_sizes, int n_in,
                              void* d_out, int out_size)
{
    const float* preds   = (const float*)d_in[0];
    const float* targets = (const float*)d_in[1];
    const int B = in_sizes[0] / 384;   // 6 * 64 floats per batch

    cudaMemsetAsync(d_out, 0, sizeof(float));
    const long long threads = (long long)B * 8;
    const int grid = (int)((threads + BLOCK - 1) / BLOCK);
    emd_kernel<<<grid, BLOCK>>>(preds, targets, (float*)d_out, B);
}